// round 16
// baseline (speedup 1.0000x reference)
#include <cuda_runtime.h>
#include <cuda_fp16.h>
#include <math.h>

#define Bsz 2
#define Ssz 2048
#define Dsz 1024
#define Hn  16
#define DHs 64
#define Mrows (Bsz*Ssz)

// Scratch (static device globals; no runtime allocation)
__device__ unsigned g_wq16[(Dsz/2)*Dsz];  // fp16-packed k-pairs, pi64 n-permute
__device__ unsigned g_wk16[(Dsz/2)*Dsz];
__device__ unsigned g_wv16[(Dsz/2)*Dsz];
__device__ unsigned g_wo16[(Dsz/2)*Dsz];
__device__ unsigned g_q16[Mrows*Dsz/2];    // [B,H,S,32w]
__device__ unsigned g_k16[Mrows*Dsz/2];    // [B,H,32(dd),S]
__device__ unsigned g_v16[Mrows*Dsz/2];    // [B,H,S/2(w),64]
__device__ unsigned g_o16[Mrows*Dsz/2];    // [M,512w]

// ---------------------------------------------------------------------------
// helpers
// ---------------------------------------------------------------------------
__device__ __forceinline__ float ex2(float x) {
    float r; asm("ex2.approx.ftz.f32 %0, %1;" : "=f"(r) : "f"(x)); return r;
}
__device__ __forceinline__ unsigned packh2(float lo, float hi) {
    __half2 h = __floats2half2_rn(lo, hi);
    return *reinterpret_cast<unsigned*>(&h);
}
__device__ __forceinline__ void mma_f16(float* c, const unsigned* a, const unsigned* b) {
    asm volatile(
        "mma.sync.aligned.m16n8k16.row.col.f32.f16.f16.f32 "
        "{%0,%1,%2,%3}, {%4,%5,%6,%7}, {%8,%9}, {%0,%1,%2,%3};"
        : "+f"(c[0]), "+f"(c[1]), "+f"(c[2]), "+f"(c[3])
        : "r"(a[0]), "r"(a[1]), "r"(a[2]), "r"(a[3]), "r"(b[0]), "r"(b[1]));
}
__device__ __forceinline__ void cp_async16(void* smem, const void* gmem) {
    unsigned s = (unsigned)__cvta_generic_to_shared(smem);
    asm volatile("cp.async.cg.shared.global [%0], [%1], 16;" :: "r"(s), "l"(gmem));
}
#define CP_COMMIT() asm volatile("cp.async.commit_group;")
#define CP_WAIT1()  asm volatile("cp.async.wait_group 1;")
#define CP_WAIT0()  asm volatile("cp.async.wait_group 0;")

// ---------------------------------------------------------------------------
// Weight convert, all four in one launch (R13/R14, validated).
// ---------------------------------------------------------------------------
__global__ void cvt_w16x4(const float* __restrict__ s0, const float* __restrict__ s1,
                          const float* __restrict__ s2, const float* __restrict__ s3,
                          unsigned* __restrict__ d0, unsigned* __restrict__ d1,
                          unsigned* __restrict__ d2, unsigned* __restrict__ d3)
{
    int wsel = blockIdx.x >> 9;
    const float* in = (wsel == 0) ? s0 : (wsel == 1) ? s1 : (wsel == 2) ? s2 : s3;
    unsigned* out   = (wsel == 0) ? d0 : (wsel == 1) ? d1 : (wsel == 2) ? d2 : d3;
    int gid = (blockIdx.x & 511) * 256 + threadIdx.x;
    int kk = gid >> 8;
    int n  = (gid & 255) * 4;
    float4 v0 = *(const float4*)&in[(size_t)(2*kk)     * Dsz + n];
    float4 v1 = *(const float4*)&in[(size_t)(2*kk + 1) * Dsz + n];
    float a0[4] = {v0.x, v0.y, v0.z, v0.w};
    float a1[4] = {v1.x, v1.y, v1.z, v1.w};
    size_t base = (size_t)kk * Dsz + (n & ~63);
    #pragma unroll
    for (int i = 0; i < 4; i++) {
        int x = (n & 63) + i;
        int p = ((x & 7) << 3) | (x >> 3);
        out[base + p] = packh2(a0[i], a1[i]);
    }
}

// ---------------------------------------------------------------------------
// FP16 GEMM, BK=64, 2-stage cp.async, ONE __syncthreads per iteration,
// post-sync prefetch (R15, validated) + NEW: register double-buffered
// fragments — ks+1's 16 LDS issue before ks's 16 MMAs, hiding LDS latency.
// Fragment/epilogue algebra byte-identical to R13-R15 (validated).
// ---------------------------------------------------------------------------
struct GemmArgs {
    const void*     X[3];
    const unsigned* W[3];
    const float*    bias[3];
    void*           out[3];
    float           scale[3];
    int             mode[3];
};

#define APF 72                                        // fp32-A pitch (floats)
#define APW 52                                        // packed-A pitch (words)
#define GEMM_SMEM   (2*(128*APF + 32*128) * 4)        // 106,496 B
#define GEMM_SMEM16 (2*(128*APW + 32*128) * 4)        //  86,016 B

template<int A16>
__global__ __launch_bounds__(256, 2)
void gemm_f16m(GemmArgs args)
{
    extern __shared__ float sm[];
    const int APITCH = A16 ? APW : APF;
    float*    As   = sm;                              // [2][128][APITCH]
    unsigned* As16 = (unsigned*)sm;
    unsigned* Bs   = (unsigned*)(sm + 2*128*APITCH);  // [2][32][128]

    const int z = blockIdx.z;
    const void*     Xv   = args.X[z];
    const unsigned* Wh   = args.W[z];
    const float*    bias = args.bias[z];
    void*           outv = args.out[z];
    const float     scale = args.scale[z];
    const int       mode  = args.mode[z];

    const int tid  = threadIdx.x;
    const int lane = tid & 31;
    const int warp = tid >> 5;
    const int g  = lane >> 2;
    const int tg = lane & 3;
    const int m0w = (warp >> 1) * 32;
    const int n0w = (warp & 1) * 64;
    const int row0 = blockIdx.y * 128;
    const int col0 = blockIdx.x * 128;

    const int sB = ((tg & 1) << 2) | ((tg >> 1) & 1);
    const int cb = (n0w >> 2) + 2*g;

    float c[2][8][4] = {};

    auto load_stage = [&](int kt, int st) {           // kt in 64-wide units
        unsigned* Bd = Bs + st*32*128;
        if (A16) {
            unsigned* Ad = As16 + st*128*APW;
            const unsigned* X16 = (const unsigned*)Xv;
            #pragma unroll
            for (int i = 0; i < 4; i++) {
                int idx = tid + i*256;
                int r = idx >> 3, wc = idx & 7;
                cp_async16(&Ad[r*APW + wc*4],
                           &X16[(size_t)(row0 + r)*(Dsz/2) + kt*32 + wc*4]);
            }
        } else {
            float* Ad = As + st*128*APF;
            const float* X = (const float*)Xv;
            #pragma unroll
            for (int i = 0; i < 8; i++) {
                int idx = tid + i*256;
                int r = idx >> 4, c4 = idx & 15;
                cp_async16(&Ad[r*APF + c4*4],
                           &X[(size_t)(row0 + r)*Dsz + kt*64 + c4*4]);
            }
        }
        #pragma unroll
        for (int i = 0; i < 4; i++) {
            int idx = tid + i*256;
            int r = idx >> 5, cc = idx & 31;
            int s = ((r & 1) << 2) | ((r >> 1) & 1);
            cp_async16(&Bd[r*128 + ((cc ^ s) << 2)],
                       &Wh[(size_t)(kt*32 + r)*Dsz + col0 + (cc << 2)]);
        }
    };

    load_stage(0, 0);
    CP_COMMIT();

    const int NT = Dsz / 64;   // 16
    for (int kt = 0; kt < NT; kt++) {
        int p = kt & 1;
        CP_WAIT0();
        __syncthreads();                 // stage p ready; all warps done with p^1
        if (kt + 1 < NT) {
            load_stage(kt + 1, p ^ 1);   // overlaps compute below
            CP_COMMIT();
        }

        const unsigned* Bp = Bs + p*32*128;
        const unsigned* Ap16 = As16 + p*128*APW;
        const float*    Apf  = As + p*128*APF;

        // fragment double-buffers: [2][...]
        unsigned bwb[2][16];
        unsigned afb[2][8];

        // load fragments for a ks-step into buffer fb (unrolled -> regs)
        auto frag_load = [&](int ks, int fb) {
            const unsigned* Br0 = &Bp[(8*ks + tg) * 128];
            const unsigned* Br1 = &Bp[(8*ks + tg + 4) * 128];
            *(uint4*)&bwb[fb][0]  = *(const uint4*)&Br0[((cb)     ^ sB) << 2];
            *(uint4*)&bwb[fb][4]  = *(const uint4*)&Br0[((cb + 1) ^ sB) << 2];
            *(uint4*)&bwb[fb][8]  = *(const uint4*)&Br1[((cb)     ^ sB) << 2];
            *(uint4*)&bwb[fb][12] = *(const uint4*)&Br1[((cb + 1) ^ sB) << 2];
            if (A16) {
                #pragma unroll
                for (int mi = 0; mi < 2; mi++) {
                    int r = m0w + mi*16 + g;
                    afb[fb][mi*4+0] = Ap16[r*APW + 8*ks + tg];
                    afb[fb][mi*4+1] = Ap16[(r+8)*APW + 8*ks + tg];
                    afb[fb][mi*4+2] = Ap16[r*APW + 8*ks + tg + 4];
                    afb[fb][mi*4+3] = Ap16[(r+8)*APW + 8*ks + tg + 4];
                }
            } else {
                #pragma unroll
                for (int mi = 0; mi < 2; mi++) {
                    int r = m0w + mi*16 + g;
                    int kc = 16*ks + 2*tg;
                    float2 p00 = *(const float2*)&Apf[r*APF + kc];
                    float2 p01 = *(const float2*)&Apf[(r+8)*APF + kc];
                    float2 p10 = *(const float2*)&Apf[r*APF + kc + 8];
                    float2 p11 = *(const float2*)&Apf[(r+8)*APF + kc + 8];
                    afb[fb][mi*4+0] = packh2(p00.x, p00.y);
                    afb[fb][mi*4+1] = packh2(p01.x, p01.y);
                    afb[fb][mi*4+2] = packh2(p10.x, p10.y);
                    afb[fb][mi*4+3] = packh2(p11.x, p11.y);
                }
            }
        };

        frag_load(0, 0);
        #pragma unroll
        for (int ks = 0; ks < 4; ks++) {
            int cur = ks & 1;
            if (ks < 3) frag_load(ks + 1, cur ^ 1);   // issue next LDS before MMAs
            #pragma unroll
            for (int mi = 0; mi < 2; mi++)
                #pragma unroll
                for (int ni = 0; ni < 8; ni++) {
                    unsigned bf[2] = { bwb[cur][ni], bwb[cur][8 + ni] };
                    mma_f16(c[mi][ni], &afb[cur][mi*4], bf);
                }
        }
    }

    // epilogue (column mapping: ni -> n0w + ni*8 + g; validated R7/R11-R15)
    #pragma unroll
    for (int mi = 0; mi < 2; mi++) {
        #pragma unroll
        for (int ni = 0; ni < 8; ni++) {
            int cc = col0 + n0w + ni*8 + 2*tg;
            float bx = bias[cc], by = bias[cc+1];
            float vx0 = (c[mi][ni][0] + bx) * scale;
            float vy0 = (c[mi][ni][1] + by) * scale;
            float vx1 = (c[mi][ni][2] + bx) * scale;
            float vy1 = (c[mi][ni][3] + by) * scale;
            int r0_ = row0 + m0w + mi*16 + g;

            if (mode == 0) {
                float* out = (float*)outv;
                *(float2*)&out[(size_t)r0_ * Dsz + cc]     = make_float2(vx0, vy0);
                *(float2*)&out[(size_t)(r0_+8) * Dsz + cc] = make_float2(vx1, vy1);
            } else if (mode == 1) {
                unsigned* o16 = (unsigned*)outv;
                int h_ = cc >> 6, dh = cc & (DHs-1);
                int b0_ = r0_ >> 11, s0 = r0_ & (Ssz-1);
                size_t base0 = (((size_t)(b0_*Hn + h_) * Ssz) + s0) * 32 + (dh >> 1);
                o16[base0]        = packh2(vx0, vy0);
                o16[base0 + 8*32] = packh2(vx1, vy1);
            } else if (mode == 2) {
                unsigned* o16 = (unsigned*)outv;
                int h_ = cc >> 6, dh = cc & (DHs-1);
                int b_ = r0_ >> 11, s0 = r0_ & (Ssz-1);
                int w = (((s0 & 63) >> 4) << 3) | (s0 & 7);
                int p0 = ((dh & 7) << 3) | (dh >> 3);
                size_t idx = ((size_t)(b_*Hn + h_) * (Ssz/2)
                              + ((size_t)(s0 >> 6) << 5) + w) * 64 + p0;
                o16[idx]     = packh2(vx0, vx1);
                o16[idx + 8] = packh2(vy0, vy1);
            } else {
                unsigned* o16 = (unsigned*)outv;
                int h_ = cc >> 6, dd = (cc & (DHs-1)) >> 1;
                int b0_ = r0_ >> 11;
                size_t base = ((size_t)(b0_*Hn + h_) * 32 + dd) * Ssz;
                o16[base + (r0_ & (Ssz-1))]     = packh2(vx0, vy0);
                o16[base + ((r0_+8) & (Ssz-1))] = packh2(vx1, vy1);
            }
        }
    }
}

// ---------------------------------------------------------------------------
// FP16 flash attention — UNCHANGED from R14/R15 (at fp16 mma.sync roofline).
// ---------------------------------------------------------------------------
#define ATTN_SMEM (6*32*64*4)   // 49,152 B

__global__ __launch_bounds__(256, 2)
void attn_f16(const unsigned* __restrict__ Q16, const unsigned* __restrict__ K16,
              const unsigned* __restrict__ V16, unsigned* __restrict__ O16)
{
    extern __shared__ unsigned smu[];
    unsigned* Kt = smu;               // [3][32][64]
    unsigned* Vs = smu + 3*32*64;     // [3][32][64]

    const int tid  = threadIdx.x;
    const int lane = tid & 31;
    const int warp = tid >> 5;
    const int g  = lane >> 2;
    const int tg = lane & 3;
    const int r0 = warp * 16 + g;

    const int q0 = blockIdx.x * 128;
    const int h = blockIdx.y, b = blockIdx.z;
    const size_t bh = (size_t)(b*Hn + h);
    const unsigned* Qg = Q16 + bh * Ssz * 32;
    const unsigned* Kg = K16 + bh * 32 * Ssz;
    const unsigned* Vg = V16 + bh * (Ssz/2) * 64;

    const int sig = (tg & 1) | ((tg & 2) << 1);
    const int pk0 = ((2*g)     ^ sig) << 2;
    const int pk1 = ((2*g + 1) ^ sig) << 2;

    unsigned aq[4][4];
    {
        const unsigned* Qw0 = &Qg[(size_t)(q0 + r0) * 32];
        const unsigned* Qw1 = &Qg[(size_t)(q0 + r0 + 8) * 32];
        #pragma unroll
        for (int ks = 0; ks < 4; ks++) {
            aq[ks][0] = Qw0[8*ks + tg];
            aq[ks][1] = Qw1[8*ks + tg];
            aq[ks][2] = Qw0[8*ks + tg + 4];
            aq[ks][3] = Qw1[8*ks + tg + 4];
        }
    }

    auto load_tile = [&](int t0, int stage) {
        unsigned* Kd = Kt + stage*32*64;
        unsigned* Vd = Vs + stage*32*64;
        #pragma unroll
        for (int i = 0; i < 2; i++) {
            int idx = tid + i*256;
            int w = idx >> 4, c = idx & 15;
            int sk = (w & 1) | ((w & 2) << 1);
            cp_async16(&Kd[w*64 + ((c ^ sk) << 2)],
                       &Kg[(size_t)w * Ssz + t0 + 4*c]);
            int sv = ((w >> 3) & 1) | (((w >> 3) & 2) << 1);
            cp_async16(&Vd[w*64 + ((c ^ sv) << 2)],
                       &Vg[(size_t)(((t0 >> 6) << 5) + w) * 64 + 4*c]);
        }
    };

    load_tile(0, 0);   CP_COMMIT();
    load_tile(64, 1);  CP_COMMIT();

    float o[8][4] = {};
    float m0 = -1e30f, m1 = -1e30f, l0 = 0.0f, l1 = 0.0f;

    const int NTILE = Ssz / 64;   // 32
    int st = 0, st2 = 2;
    for (int t = 0; t < NTILE; t++) {
        if (t + 1 < NTILE) { CP_WAIT1(); } else { CP_WAIT0(); }
        __syncthreads();

        if (t + 2 < NTILE) {
            load_tile((t+2)*64, st2);
            CP_COMMIT();
        }

        const unsigned* Ktp = Kt + st*32*64;
        const unsigned* Vsp = Vs + st*32*64;

        float s[8][4] = {};
        #pragma unroll
        for (int ks = 0; ks < 4; ks++) {
            unsigned bw0[8], bw1[8];
            const unsigned* Kr0 = &Ktp[(8*ks + tg)*64];
            const unsigned* Kr1 = &Ktp[(8*ks + tg + 4)*64];
            *(uint4*)&bw0[0] = *(const uint4*)&Kr0[pk0];
            *(uint4*)&bw0[4] = *(const uint4*)&Kr0[pk1];
            *(uint4*)&bw1[0] = *(const uint4*)&Kr1[pk0];
            *(uint4*)&bw1[4] = *(const uint4*)&Kr1[pk1];
            #pragma unroll
            for (int nt = 0; nt < 8; nt++) {
                unsigned bf[2] = { bw0[nt], bw1[nt] };
                mma_f16(s[nt], aq[ks], bf);
            }
        }

        float rm0 = -1e30f, rm1 = -1e30f;
        #pragma unroll
        for (int nt = 0; nt < 8; nt++) {
            rm0 = fmaxf(rm0, fmaxf(s[nt][0], s[nt][1]));
            rm1 = fmaxf(rm1, fmaxf(s[nt][2], s[nt][3]));
        }
        rm0 = fmaxf(rm0, __shfl_xor_sync(0xffffffffu, rm0, 1));
        rm0 = fmaxf(rm0, __shfl_xor_sync(0xffffffffu, rm0, 2));
        rm1 = fmaxf(rm1, __shfl_xor_sync(0xffffffffu, rm1, 1));
        rm1 = fmaxf(rm1, __shfl_xor_sync(0xffffffffu, rm1, 2));

        float mn0 = fmaxf(m0, rm0), mn1 = fmaxf(m1, rm1);
        float al0 = ex2(m0 - mn0), al1 = ex2(m1 - mn1);
        m0 = mn0; m1 = mn1;

        float rs0 = 0.0f, rs1 = 0.0f;
        #pragma unroll
        for (int nt = 0; nt < 8; nt++) {
            s[nt][0] = ex2(s[nt][0] - m0);
            s[nt][1] = ex2(s[nt][1] - m0);
            s[nt][2] = ex2(s[nt][2] - m1);
            s[nt][3] = ex2(s[nt][3] - m1);
            rs0 += s[nt][0] + s[nt][1];
            rs1 += s[nt][2] + s[nt][3];
        }
        rs0 += __shfl_xor_sync(0xffffffffu, rs0, 1);
        rs0 += __shfl_xor_sync(0xffffffffu, rs0, 2);
        rs1 += __shfl_xor_sync(0xffffffffu, rs1, 1);
        rs1 += __shfl_xor_sync(0xffffffffu, rs1, 2);

        l0 = l0 * al0 + rs0;
        l1 = l1 * al1 + rs1;
        #pragma unroll
        for (int nt = 0; nt < 8; nt++) {
            o[nt][0] *= al0; o[nt][1] *= al0;
            o[nt][2] *= al1; o[nt][3] *= al1;
        }

        unsigned pf[8][2];
        #pragma unroll
        for (int nt = 0; nt < 8; nt++) {
            pf[nt][0] = packh2(s[nt][0], s[nt][1]);
            pf[nt][1] = packh2(s[nt][2], s[nt][3]);
        }

        #pragma unroll
        for (int ks = 0; ks < 4; ks++) {
            unsigned bw0[8], bw1[8];
            const unsigned* Vr0 = &Vsp[(8*tg + 2*ks)*64];
            const unsigned* Vr1 = &Vsp[(8*tg + 2*ks + 1)*64];
            *(uint4*)&bw0[0] = *(const uint4*)&Vr0[pk0];
            *(uint4*)&bw0[4] = *(const uint4*)&Vr0[pk1];
            *(uint4*)&bw1[0] = *(const uint4*)&Vr1[pk0];
            *(uint4*)&bw1[4] = *(const uint4*)&Vr1[pk1];
            unsigned a[4] = { pf[2*ks][0], pf[2*ks][1], pf[2*ks+1][0], pf[2*ks+1][1] };
            #pragma unroll
            for (int nt = 0; nt < 8; nt++) {
                unsigned bf[2] = { bw0[nt], bw1[nt] };
                mma_f16(o[nt], a, bf);
            }
        }

        st = (st == 2) ? 0 : st + 1;
        st2 = (st2 == 2) ? 0 : st2 + 1;
    }

    float inv0 = 1.0f / l0, inv1 = 1.0f / l1;
    size_t ob0 = ((size_t)(b*Ssz + q0 + r0)) * (Dsz/2) + h*32;
    size_t ob1 = ((size_t)(b*Ssz + q0 + r0 + 8)) * (Dsz/2) + h*32;
    #pragma unroll
    for (int nt = 0; nt < 8; nt++) {
        int w = nt*4 + tg;
        O16[ob0 + w] = packh2(o[nt][0]*inv0, o[nt][1]*inv0);
        O16[ob1 + w] = packh2(o[nt][2]*inv1, o[nt][3]*inv1);
    }
}

// ---------------------------------------------------------------------------

extern "C" void kernel_launch(void* const* d_in, const int* in_sizes, int n_in,
                              void* d_out, int out_size)
{
    (void)in_sizes; (void)n_in; (void)out_size;
    const float* queries = (const float*)d_in[0];
    const float* keys    = (const float*)d_in[1];
    const float* values  = (const float*)d_in[2];
    const float* Wq = (const float*)d_in[3];
    const float* bq = (const float*)d_in[4];
    const float* Wk = (const float*)d_in[5];
    const float* bk = (const float*)d_in[6];
    const float* Wv = (const float*)d_in[7];
    const float* bv = (const float*)d_in[8];
    const float* Wo = (const float*)d_in[9];
    const float* bo = (const float*)d_in[10];
    float* out = (float*)d_out;

    void *pwq,*pwk,*pwv,*pwo,*pq,*pk,*pv,*po;
    cudaGetSymbolAddress(&pwq, g_wq16); cudaGetSymbolAddress(&pwk, g_wk16);
    cudaGetSymbolAddress(&pwv, g_wv16); cudaGetSymbolAddress(&pwo, g_wo16);
    cudaGetSymbolAddress(&pq, g_q16);   cudaGetSymbolAddress(&pk, g_k16);
    cudaGetSymbolAddress(&pv, g_v16);   cudaGetSymbolAddress(&po, g_o16);

    cudaFuncSetAttribute((const void*)gemm_f16m<0>, cudaFuncAttributeMaxDynamicSharedMemorySize, GEMM_SMEM);
    cudaFuncSetAttribute((const void*)gemm_f16m<1>, cudaFuncAttributeMaxDynamicSharedMemorySize, GEMM_SMEM16);
    cudaFuncSetAttribute((const void*)attn_f16,     cudaFuncAttributeMaxDynamicSharedMemorySize, ATTN_SMEM);

    // launch 1: all four weight converts
    cvt_w16x4<<<2048, 256>>>(Wq, Wk, Wv, Wo,
                             (unsigned*)pwq, (unsigned*)pwk,
                             (unsigned*)pwv, (unsigned*)pwo);

    const float qscale = 0.125f * 1.4426950408889634f;   // log2e / sqrt(64)

    // launch 2: merged Q/K/V projections (grid.z selects mode)
    GemmArgs qkv;
    qkv.X[0] = queries; qkv.X[1] = keys; qkv.X[2] = values;
    qkv.W[0] = (const unsigned*)pwq; qkv.W[1] = (const unsigned*)pwk; qkv.W[2] = (const unsigned*)pwv;
    qkv.bias[0] = bq; qkv.bias[1] = bk; qkv.bias[2] = bv;
    qkv.out[0] = pq; qkv.out[1] = pk; qkv.out[2] = pv;
    qkv.scale[0] = qscale; qkv.scale[1] = 1.0f; qkv.scale[2] = 1.0f;
    qkv.mode[0] = 1; qkv.mode[1] = 3; qkv.mode[2] = 2;
    dim3 qgrid(Dsz/128, Mrows/128, 3);   // (8, 32, 3)
    gemm_f16m<0><<<qgrid, 256, GEMM_SMEM>>>(qkv);

    // launch 3: attention
    dim3 agrid(Ssz/128, Hn, Bsz);        // (16, 16, 2)
    attn_f16<<<agrid, 256, ATTN_SMEM>>>((const unsigned*)pq, (const unsigned*)pk,
                                        (const unsigned*)pv, (unsigned*)po);

    // launch 4: final projection (pre-packed fp16 A path)
    GemmArgs fin;
    fin.X[0] = po; fin.X[1] = po; fin.X[2] = po;
    fin.W[0] = (const unsigned*)pwo; fin.W[1] = (const unsigned*)pwo; fin.W[2] = (const unsigned*)pwo;
    fin.bias[0] = bo; fin.bias[1] = bo; fin.bias[2] = bo;
    fin.out[0] = out; fin.out[1] = out; fin.out[2] = out;
    fin.scale[0] = 1.0f; fin.scale[1] = 1.0f; fin.scale[2] = 1.0f;
    fin.mode[0] = 0; fin.mode[1] = 0; fin.mode[2] = 0;
    dim3 fgrid(Dsz/128, Mrows/128, 1);
    gemm_f16m<1><<<fgrid, 256, GEMM_SMEM16>>>(fin);
}

// round 17
// speedup vs baseline: 1.0220x; 1.0220x over previous
#include <cuda_runtime.h>
#include <cuda_fp16.h>
#include <math.h>

#define Bsz 2
#define Ssz 2048
#define Dsz 1024
#define Hn  16
#define DHs 64
#define Mrows (Bsz*Ssz)

// Scratch (static device globals; no runtime allocation)
__device__ unsigned g_wq16[(Dsz/2)*Dsz];  // fp16-packed k-pairs, pi64 n-permute
__device__ unsigned g_wk16[(Dsz/2)*Dsz];
__device__ unsigned g_wv16[(Dsz/2)*Dsz];
__device__ unsigned g_wo16[(Dsz/2)*Dsz];
__device__ unsigned g_q16[Mrows*Dsz/2];    // [B,H,S,32w]
__device__ unsigned g_k16[Mrows*Dsz/2];    // [B,H,32(dd),S]
__device__ unsigned g_v16[Mrows*Dsz/2];    // [B,H,S/2(w),64]
__device__ unsigned g_o16[Mrows*Dsz/2];    // [M,512w]

// ---------------------------------------------------------------------------
// helpers
// ---------------------------------------------------------------------------
__device__ __forceinline__ float ex2(float x) {
    float r; asm("ex2.approx.ftz.f32 %0, %1;" : "=f"(r) : "f"(x)); return r;
}
__device__ __forceinline__ unsigned packh2(float lo, float hi) {
    __half2 h = __floats2half2_rn(lo, hi);
    return *reinterpret_cast<unsigned*>(&h);
}
__device__ __forceinline__ void mma_f16(float* c, const unsigned* a, const unsigned* b) {
    asm volatile(
        "mma.sync.aligned.m16n8k16.row.col.f32.f16.f16.f32 "
        "{%0,%1,%2,%3}, {%4,%5,%6,%7}, {%8,%9}, {%0,%1,%2,%3};"
        : "+f"(c[0]), "+f"(c[1]), "+f"(c[2]), "+f"(c[3])
        : "r"(a[0]), "r"(a[1]), "r"(a[2]), "r"(a[3]), "r"(b[0]), "r"(b[1]));
}
__device__ __forceinline__ void cp_async16(void* smem, const void* gmem) {
    unsigned s = (unsigned)__cvta_generic_to_shared(smem);
    asm volatile("cp.async.cg.shared.global [%0], [%1], 16;" :: "r"(s), "l"(gmem));
}
#define CP_COMMIT() asm volatile("cp.async.commit_group;")
#define CP_WAIT0()  asm volatile("cp.async.wait_group 0;")
#define CP_WAIT1()  asm volatile("cp.async.wait_group 1;")

// ---------------------------------------------------------------------------
// Weight convert, all four in one launch (R13-R15, validated).
// ---------------------------------------------------------------------------
__global__ void cvt_w16x4(const float* __restrict__ s0, const float* __restrict__ s1,
                          const float* __restrict__ s2, const float* __restrict__ s3,
                          unsigned* __restrict__ d0, unsigned* __restrict__ d1,
                          unsigned* __restrict__ d2, unsigned* __restrict__ d3)
{
    int wsel = blockIdx.x >> 9;
    const float* in = (wsel == 0) ? s0 : (wsel == 1) ? s1 : (wsel == 2) ? s2 : s3;
    unsigned* out   = (wsel == 0) ? d0 : (wsel == 1) ? d1 : (wsel == 2) ? d2 : d3;
    int gid = (blockIdx.x & 511) * 256 + threadIdx.x;
    int kk = gid >> 8;
    int n  = (gid & 255) * 4;
    float4 v0 = *(const float4*)&in[(size_t)(2*kk)     * Dsz + n];
    float4 v1 = *(const float4*)&in[(size_t)(2*kk + 1) * Dsz + n];
    float a0[4] = {v0.x, v0.y, v0.z, v0.w};
    float a1[4] = {v1.x, v1.y, v1.z, v1.w};
    size_t base = (size_t)kk * Dsz + (n & ~63);
    #pragma unroll
    for (int i = 0; i < 4; i++) {
        int x = (n & 63) + i;
        int p = ((x & 7) << 3) | (x >> 3);
        out[base + p] = packh2(a0[i], a1[i]);
    }
}

// ---------------------------------------------------------------------------
// FP16 GEMM, R15 main-loop structure (best measured) with 64-row M-tile:
// warp tile 16x64, C = 32 regs/thread -> __launch_bounds__(256,3) -> 3 CTAs/SM.
// BK=64, 2-stage cp.async, ONE __syncthreads per iteration, post-sync prefetch.
// Fragment/epilogue algebra identical to R13-R15 with mi=0 only.
// ---------------------------------------------------------------------------
struct GemmArgs {
    const void*     X[3];
    const unsigned* W[3];
    const float*    bias[3];
    void*           out[3];
    float           scale[3];
    int             mode[3];
};

#define APF 72                                        // fp32-A pitch (floats)
#define APW 52                                        // packed-A pitch (words)
#define GEMM_SMEM   (2*(64*APF + 32*128) * 4)         // 69,632 B -> 3 CTAs
#define GEMM_SMEM16 (2*(64*APW + 32*128) * 4)         // 52,224 B -> 3 CTAs

template<int A16>
__global__ __launch_bounds__(256, 3)
void gemm_f16m(GemmArgs args)
{
    extern __shared__ float sm[];
    const int APITCH = A16 ? APW : APF;
    float*    As   = sm;                              // [2][64][APITCH]
    unsigned* As16 = (unsigned*)sm;
    unsigned* Bs   = (unsigned*)(sm + 2*64*APITCH);   // [2][32][128]

    const int z = blockIdx.z;
    const void*     Xv   = args.X[z];
    const unsigned* Wh   = args.W[z];
    const float*    bias = args.bias[z];
    void*           outv = args.out[z];
    const float     scale = args.scale[z];
    const int       mode  = args.mode[z];

    const int tid  = threadIdx.x;
    const int lane = tid & 31;
    const int warp = tid >> 5;
    const int g  = lane >> 2;
    const int tg = lane & 3;
    const int m0w = (warp >> 1) * 16;                 // 4 M-warps x 16 rows
    const int n0w = (warp & 1) * 64;
    const int row0 = blockIdx.y * 64;
    const int col0 = blockIdx.x * 128;

    const int sB = ((tg & 1) << 2) | ((tg >> 1) & 1);
    const int cb = (n0w >> 2) + 2*g;

    float c[8][4] = {};

    auto load_stage = [&](int kt, int st) {           // kt in 64-wide units
        unsigned* Bd = Bs + st*32*128;
        if (A16) {
            unsigned* Ad = As16 + st*64*APW;
            const unsigned* X16 = (const unsigned*)Xv;
            #pragma unroll
            for (int i = 0; i < 2; i++) {
                int idx = tid + i*256;
                int r = idx >> 3, wc = idx & 7;
                cp_async16(&Ad[r*APW + wc*4],
                           &X16[(size_t)(row0 + r)*(Dsz/2) + kt*32 + wc*4]);
            }
        } else {
            float* Ad = As + st*64*APF;
            const float* X = (const float*)Xv;
            #pragma unroll
            for (int i = 0; i < 4; i++) {
                int idx = tid + i*256;
                int r = idx >> 4, c4 = idx & 15;
                cp_async16(&Ad[r*APF + c4*4],
                           &X[(size_t)(row0 + r)*Dsz + kt*64 + c4*4]);
            }
        }
        #pragma unroll
        for (int i = 0; i < 4; i++) {
            int idx = tid + i*256;
            int r = idx >> 5, cc = idx & 31;
            int s = ((r & 1) << 2) | ((r >> 1) & 1);
            cp_async16(&Bd[r*128 + ((cc ^ s) << 2)],
                       &Wh[(size_t)(kt*32 + r)*Dsz + col0 + (cc << 2)]);
        }
    };

    load_stage(0, 0);
    CP_COMMIT();

    const int NT = Dsz / 64;   // 16
    for (int kt = 0; kt < NT; kt++) {
        int p = kt & 1;
        CP_WAIT0();
        __syncthreads();                 // stage p ready; all warps done with p^1
        if (kt + 1 < NT) {
            load_stage(kt + 1, p ^ 1);   // overlaps compute below
            CP_COMMIT();
        }

        const unsigned* Bp = Bs + p*32*128;
        #pragma unroll
        for (int ks = 0; ks < 4; ks++) {
            unsigned bw0[8], bw1[8];
            {
                const unsigned* Br0 = &Bp[(8*ks + tg) * 128];
                const unsigned* Br1 = &Bp[(8*ks + tg + 4) * 128];
                *(uint4*)&bw0[0] = *(const uint4*)&Br0[((cb)     ^ sB) << 2];
                *(uint4*)&bw0[4] = *(const uint4*)&Br0[((cb + 1) ^ sB) << 2];
                *(uint4*)&bw1[0] = *(const uint4*)&Br1[((cb)     ^ sB) << 2];
                *(uint4*)&bw1[4] = *(const uint4*)&Br1[((cb + 1) ^ sB) << 2];
            }
            unsigned af[4];
            if (A16) {
                const unsigned* Ap16 = As16 + p*64*APW;
                int r = m0w + g;
                af[0] = Ap16[r*APW + 8*ks + tg];
                af[1] = Ap16[(r+8)*APW + 8*ks + tg];
                af[2] = Ap16[r*APW + 8*ks + tg + 4];
                af[3] = Ap16[(r+8)*APW + 8*ks + tg + 4];
            } else {
                const float* Ap = As + p*64*APF;
                int r = m0w + g;
                int kc = 16*ks + 2*tg;
                float2 p00 = *(const float2*)&Ap[r*APF + kc];
                float2 p01 = *(const float2*)&Ap[(r+8)*APF + kc];
                float2 p10 = *(const float2*)&Ap[r*APF + kc + 8];
                float2 p11 = *(const float2*)&Ap[(r+8)*APF + kc + 8];
                af[0] = packh2(p00.x, p00.y);
                af[1] = packh2(p01.x, p01.y);
                af[2] = packh2(p10.x, p10.y);
                af[3] = packh2(p11.x, p11.y);
            }
            #pragma unroll
            for (int ni = 0; ni < 8; ni++) {
                unsigned bf[2] = { bw0[ni], bw1[ni] };
                mma_f16(c[ni], af, bf);
            }
        }
    }

    // epilogue (column mapping: ni -> n0w + ni*8 + g; validated R7/R11-R15; mi=0)
    #pragma unroll
    for (int ni = 0; ni < 8; ni++) {
        int cc = col0 + n0w + ni*8 + 2*tg;
        float bx = bias[cc], by = bias[cc+1];
        float vx0 = (c[ni][0] + bx) * scale;
        float vy0 = (c[ni][1] + by) * scale;
        float vx1 = (c[ni][2] + bx) * scale;
        float vy1 = (c[ni][3] + by) * scale;
        int r0_ = row0 + m0w + g;

        if (mode == 0) {
            float* out = (float*)outv;
            *(float2*)&out[(size_t)r0_ * Dsz + cc]     = make_float2(vx0, vy0);
            *(float2*)&out[(size_t)(r0_+8) * Dsz + cc] = make_float2(vx1, vy1);
        } else if (mode == 1) {
            unsigned* o16 = (unsigned*)outv;
            int h_ = cc >> 6, dh = cc & (DHs-1);
            int b0_ = r0_ >> 11, s0 = r0_ & (Ssz-1);
            size_t base0 = (((size_t)(b0_*Hn + h_) * Ssz) + s0) * 32 + (dh >> 1);
            o16[base0]        = packh2(vx0, vy0);
            o16[base0 + 8*32] = packh2(vx1, vy1);
        } else if (mode == 2) {
            unsigned* o16 = (unsigned*)outv;
            int h_ = cc >> 6, dh = cc & (DHs-1);
            int b_ = r0_ >> 11, s0 = r0_ & (Ssz-1);
            int w = (((s0 & 63) >> 4) << 3) | (s0 & 7);
            int p0 = ((dh & 7) << 3) | (dh >> 3);
            size_t idx = ((size_t)(b_*Hn + h_) * (Ssz/2)
                          + ((size_t)(s0 >> 6) << 5) + w) * 64 + p0;
            o16[idx]     = packh2(vx0, vx1);
            o16[idx + 8] = packh2(vy0, vy1);
        } else {
            unsigned* o16 = (unsigned*)outv;
            int h_ = cc >> 6, dd = (cc & (DHs-1)) >> 1;
            int b0_ = r0_ >> 11;
            size_t base = ((size_t)(b0_*Hn + h_) * 32 + dd) * Ssz;
            o16[base + (r0_ & (Ssz-1))]     = packh2(vx0, vy0);
            o16[base + ((r0_+8) & (Ssz-1))] = packh2(vx1, vy1);
        }
    }
}

// ---------------------------------------------------------------------------
// FP16 flash attention — UNCHANGED from R14/R15 (at fp16 mma.sync roofline).
// ---------------------------------------------------------------------------
#define ATTN_SMEM (6*32*64*4)   // 49,152 B

__global__ __launch_bounds__(256, 2)
void attn_f16(const unsigned* __restrict__ Q16, const unsigned* __restrict__ K16,
              const unsigned* __restrict__ V16, unsigned* __restrict__ O16)
{
    extern __shared__ unsigned smu[];
    unsigned* Kt = smu;               // [3][32][64]
    unsigned* Vs = smu + 3*32*64;     // [3][32][64]

    const int tid  = threadIdx.x;
    const int lane = tid & 31;
    const int warp = tid >> 5;
    const int g  = lane >> 2;
    const int tg = lane & 3;
    const int r0 = warp * 16 + g;

    const int q0 = blockIdx.x * 128;
    const int h = blockIdx.y, b = blockIdx.z;
    const size_t bh = (size_t)(b*Hn + h);
    const unsigned* Qg = Q16 + bh * Ssz * 32;
    const unsigned* Kg = K16 + bh * 32 * Ssz;
    const unsigned* Vg = V16 + bh * (Ssz/2) * 64;

    const int sig = (tg & 1) | ((tg & 2) << 1);
    const int pk0 = ((2*g)     ^ sig) << 2;
    const int pk1 = ((2*g + 1) ^ sig) << 2;

    unsigned aq[4][4];
    {
        const unsigned* Qw0 = &Qg[(size_t)(q0 + r0) * 32];
        const unsigned* Qw1 = &Qg[(size_t)(q0 + r0 + 8) * 32];
        #pragma unroll
        for (int ks = 0; ks < 4; ks++) {
            aq[ks][0] = Qw0[8*ks + tg];
            aq[ks][1] = Qw1[8*ks + tg];
            aq[ks][2] = Qw0[8*ks + tg + 4];
            aq[ks][3] = Qw1[8*ks + tg + 4];
        }
    }

    auto load_tile = [&](int t0, int stage) {
        unsigned* Kd = Kt + stage*32*64;
        unsigned* Vd = Vs + stage*32*64;
        #pragma unroll
        for (int i = 0; i < 2; i++) {
            int idx = tid + i*256;
            int w = idx >> 4, c = idx & 15;
            int sk = (w & 1) | ((w & 2) << 1);
            cp_async16(&Kd[w*64 + ((c ^ sk) << 2)],
                       &Kg[(size_t)w * Ssz + t0 + 4*c]);
            int sv = ((w >> 3) & 1) | (((w >> 3) & 2) << 1);
            cp_async16(&Vd[w*64 + ((c ^ sv) << 2)],
                       &Vg[(size_t)(((t0 >> 6) << 5) + w) * 64 + 4*c]);
        }
    };

    load_tile(0, 0);   CP_COMMIT();
    load_tile(64, 1);  CP_COMMIT();

    float o[8][4] = {};
    float m0 = -1e30f, m1 = -1e30f, l0 = 0.0f, l1 = 0.0f;

    const int NTILE = Ssz / 64;   // 32
    int st = 0, st2 = 2;
    for (int t = 0; t < NTILE; t++) {
        if (t + 1 < NTILE) { CP_WAIT1(); } else { CP_WAIT0(); }
        __syncthreads();

        if (t + 2 < NTILE) {
            load_tile((t+2)*64, st2);
            CP_COMMIT();
        }

        const unsigned* Ktp = Kt + st*32*64;
        const unsigned* Vsp = Vs + st*32*64;

        float s[8][4] = {};
        #pragma unroll
        for (int ks = 0; ks < 4; ks++) {
            unsigned bw0[8], bw1[8];
            const unsigned* Kr0 = &Ktp[(8*ks + tg)*64];
            const unsigned* Kr1 = &Ktp[(8*ks + tg + 4)*64];
            *(uint4*)&bw0[0] = *(const uint4*)&Kr0[pk0];
            *(uint4*)&bw0[4] = *(const uint4*)&Kr0[pk1];
            *(uint4*)&bw1[0] = *(const uint4*)&Kr1[pk0];
            *(uint4*)&bw1[4] = *(const uint4*)&Kr1[pk1];
            #pragma unroll
            for (int nt = 0; nt < 8; nt++) {
                unsigned bf[2] = { bw0[nt], bw1[nt] };
                mma_f16(s[nt], aq[ks], bf);
            }
        }

        float rm0 = -1e30f, rm1 = -1e30f;
        #pragma unroll
        for (int nt = 0; nt < 8; nt++) {
            rm0 = fmaxf(rm0, fmaxf(s[nt][0], s[nt][1]));
            rm1 = fmaxf(rm1, fmaxf(s[nt][2], s[nt][3]));
        }
        rm0 = fmaxf(rm0, __shfl_xor_sync(0xffffffffu, rm0, 1));
        rm0 = fmaxf(rm0, __shfl_xor_sync(0xffffffffu, rm0, 2));
        rm1 = fmaxf(rm1, __shfl_xor_sync(0xffffffffu, rm1, 1));
        rm1 = fmaxf(rm1, __shfl_xor_sync(0xffffffffu, rm1, 2));

        float mn0 = fmaxf(m0, rm0), mn1 = fmaxf(m1, rm1);
        float al0 = ex2(m0 - mn0), al1 = ex2(m1 - mn1);
        m0 = mn0; m1 = mn1;

        float rs0 = 0.0f, rs1 = 0.0f;
        #pragma unroll
        for (int nt = 0; nt < 8; nt++) {
            s[nt][0] = ex2(s[nt][0] - m0);
            s[nt][1] = ex2(s[nt][1] - m0);
            s[nt][2] = ex2(s[nt][2] - m1);
            s[nt][3] = ex2(s[nt][3] - m1);
            rs0 += s[nt][0] + s[nt][1];
            rs1 += s[nt][2] + s[nt][3];
        }
        rs0 += __shfl_xor_sync(0xffffffffu, rs0, 1);
        rs0 += __shfl_xor_sync(0xffffffffu, rs0, 2);
        rs1 += __shfl_xor_sync(0xffffffffu, rs1, 1);
        rs1 += __shfl_xor_sync(0xffffffffu, rs1, 2);

        l0 = l0 * al0 + rs0;
        l1 = l1 * al1 + rs1;
        #pragma unroll
        for (int nt = 0; nt < 8; nt++) {
            o[nt][0] *= al0; o[nt][1] *= al0;
            o[nt][2] *= al1; o[nt][3] *= al1;
        }

        unsigned pf[8][2];
        #pragma unroll
        for (int nt = 0; nt < 8; nt++) {
            pf[nt][0] = packh2(s[nt][0], s[nt][1]);
            pf[nt][1] = packh2(s[nt][2], s[nt][3]);
        }

        #pragma unroll
        for (int ks = 0; ks < 4; ks++) {
            unsigned bw0[8], bw1[8];
            const unsigned* Vr0 = &Vsp[(8*tg + 2*ks)*64];
            const unsigned* Vr1 = &Vsp[(8*tg + 2*ks + 1)*64];
            *(uint4*)&bw0[0] = *(const uint4*)&Vr0[pk0];
            *(uint4*)&bw0[4] = *(const uint4*)&Vr0[pk1];
            *(uint4*)&bw1[0] = *(const uint4*)&Vr1[pk0];
            *(uint4*)&bw1[4] = *(const uint4*)&Vr1[pk1];
            unsigned a[4] = { pf[2*ks][0], pf[2*ks][1], pf[2*ks+1][0], pf[2*ks+1][1] };
            #pragma unroll
            for (int nt = 0; nt < 8; nt++) {
                unsigned bf[2] = { bw0[nt], bw1[nt] };
                mma_f16(o[nt], a, bf);
            }
        }

        st = (st == 2) ? 0 : st + 1;
        st2 = (st2 == 2) ? 0 : st2 + 1;
    }

    float inv0 = 1.0f / l0, inv1 = 1.0f / l1;
    size_t ob0 = ((size_t)(b*Ssz + q0 + r0)) * (Dsz/2) + h*32;
    size_t ob1 = ((size_t)(b*Ssz + q0 + r0 + 8)) * (Dsz/2) + h*32;
    #pragma unroll
    for (int nt = 0; nt < 8; nt++) {
        int w = nt*4 + tg;
        O16[ob0 + w] = packh2(o[nt][0]*inv0, o[nt][1]*inv0);
        O16[ob1 + w] = packh2(o[nt][2]*inv1, o[nt][3]*inv1);
    }
}

// ---------------------------------------------------------------------------

extern "C" void kernel_launch(void* const* d_in, const int* in_sizes, int n_in,
                              void* d_out, int out_size)
{
    (void)in_sizes; (void)n_in; (void)out_size;
    const float* queries = (const float*)d_in[0];
    const float* keys    = (const float*)d_in[1];
    const float* values  = (const float*)d_in[2];
    const float* Wq = (const float*)d_in[3];
    const float* bq = (const float*)d_in[4];
    const float* Wk = (const float*)d_in[5];
    const float* bk = (const float*)d_in[6];
    const float* Wv = (const float*)d_in[7];
    const float* bv = (const float*)d_in[8];
    const float* Wo = (const float*)d_in[9];
    const float* bo = (const float*)d_in[10];
    float* out = (float*)d_out;

    void *pwq,*pwk,*pwv,*pwo,*pq,*pk,*pv,*po;
    cudaGetSymbolAddress(&pwq, g_wq16); cudaGetSymbolAddress(&pwk, g_wk16);
    cudaGetSymbolAddress(&pwv, g_wv16); cudaGetSymbolAddress(&pwo, g_wo16);
    cudaGetSymbolAddress(&pq, g_q16);   cudaGetSymbolAddress(&pk, g_k16);
    cudaGetSymbolAddress(&pv, g_v16);   cudaGetSymbolAddress(&po, g_o16);

    cudaFuncSetAttribute((const void*)gemm_f16m<0>, cudaFuncAttributeMaxDynamicSharedMemorySize, GEMM_SMEM);
    cudaFuncSetAttribute((const void*)gemm_f16m<1>, cudaFuncAttributeMaxDynamicSharedMemorySize, GEMM_SMEM16);
    cudaFuncSetAttribute((const void*)attn_f16,     cudaFuncAttributeMaxDynamicSharedMemorySize, ATTN_SMEM);

    // launch 1: all four weight converts
    cvt_w16x4<<<2048, 256>>>(Wq, Wk, Wv, Wo,
                             (unsigned*)pwq, (unsigned*)pwk,
                             (unsigned*)pwv, (unsigned*)pwo);

    const float qscale = 0.125f * 1.4426950408889634f;   // log2e / sqrt(64)

    // launch 2: merged Q/K/V projections (grid.z selects mode)
    GemmArgs qkv;
    qkv.X[0] = queries; qkv.X[1] = keys; qkv.X[2] = values;
    qkv.W[0] = (const unsigned*)pwq; qkv.W[1] = (const unsigned*)pwk; qkv.W[2] = (const unsigned*)pwv;
    qkv.bias[0] = bq; qkv.bias[1] = bk; qkv.bias[2] = bv;
    qkv.out[0] = pq; qkv.out[1] = pk; qkv.out[2] = pv;
    qkv.scale[0] = qscale; qkv.scale[1] = 1.0f; qkv.scale[2] = 1.0f;
    qkv.mode[0] = 1; qkv.mode[1] = 3; qkv.mode[2] = 2;
    dim3 qgrid(Dsz/128, Mrows/64, 3);    // (8, 64, 3)
    gemm_f16m<0><<<qgrid, 256, GEMM_SMEM>>>(qkv);

    // launch 3: attention
    dim3 agrid(Ssz/128, Hn, Bsz);        // (16, 16, 2)
    attn_f16<<<agrid, 256, ATTN_SMEM>>>((const unsigned*)pq, (const unsigned*)pk,
                                        (const unsigned*)pv, (unsigned*)po);

    // launch 4: final projection (pre-packed fp16 A path)
    GemmArgs fin;
    fin.X[0] = po; fin.X[1] = po; fin.X[2] = po;
    fin.W[0] = (const unsigned*)pwo; fin.W[1] = (const unsigned*)pwo; fin.W[2] = (const unsigned*)pwo;
    fin.bias[0] = bo; fin.bias[1] = bo; fin.bias[2] = bo;
    fin.out[0] = out; fin.out[1] = out; fin.out[2] = out;
    fin.scale[0] = 1.0f; fin.scale[1] = 1.0f; fin.scale[2] = 1.0f;
    fin.mode[0] = 0; fin.mode[1] = 0; fin.mode[2] = 0;
    dim3 fgrid(Dsz/128, Mrows/64, 1);    // (8, 64, 1)
    gemm_f16m<1><<<fgrid, 256, GEMM_SMEM16>>>(fin);
}